// round 13
// baseline (speedup 1.0000x reference)
#include <cuda_runtime.h>
#include <cuda_fp16.h>
#include <cstdint>

#define D_ 64
#define B_ 64
#define S_ 1024
#define L_ 512
#define O_ 10

typedef unsigned long long u64;

__device__ float g_vL[B_][D_];
__device__ float g_wR[B_][D_];
// fp16 E = W - I, scan-ordered, side-uniform, thread-major 64B per thread:
// g_E[(side*512+s)*4096 + tid*16 + j] = half2 E_scan[in=(lane&3)*16+j][out]
__device__ __align__(16) uint32_t g_E[2 * L_ * 4096];

// ---------- prep: thread-major fp16 E, side-uniform, vectorized stores ----------
__global__ void __launch_bounds__(256, 4) prep_kernel(
        const float* __restrict__ Wl, const float* __restrict__ Wr) {
    __shared__ float2 tile[D_ * (D_ + 1)];
    int bx = blockIdx.x;
    int side = bx >> 9;
    int s = bx & 511;
    int tid = threadIdx.x;
    if (side == 0) {
        const float2* src = (const float2*)Wl + (size_t)s * 4096;
        for (int i = tid; i < 4096; i += 256) {
            int l = i >> 6, r = i & 63;
            tile[l * 65 + r] = src[i];
        }
    } else {
        const float2* src = (const float2*)Wr + (size_t)(511 - s) * 4096;
        for (int i = tid; i < 4096; i += 256) {
            int l = i >> 6, r = i & 63;
            tile[r * 65 + l] = src[i];
        }
    }
    __syncthreads();
    int lane = tid & 31, w = tid >> 5;
    int out = w * 8 + (lane >> 2);
    int q = lane & 3;
    uint4* dst = (uint4*)(g_E + (size_t)bx * 4096 + tid * 16);
    #pragma unroll
    for (int c = 0; c < 4; c++) {
        uint4 o;
        uint32_t* op = &o.x;
        #pragma unroll
        for (int k = 0; k < 4; k++) {
            int in = q * 16 + c * 4 + k;
            float d = (in == out) ? 1.0f : 0.0f;
            float2 wv = tile[in * 65 + out];
            __half2 h = __floats2half2_rn(wv.x - d, wv.y - d);
            op[k] = *(uint32_t*)&h;
        }
        dst[c] = o;
    }
}

// profiling-only slot rotators (keep chain at launch #4)
__global__ void dummy_kernel(int v) { if (v == 12345) g_vL[0][0] = 0.f; }

// ---------- per-site partial: FULLY scalar, zero arrays ----------
#define ACC(acc, hword, uval) do {                                              \
        uint32_t _h = (hword);                                                  \
        float2 _f = __half22float2(*(__half2*)&_h);                             \
        u64 _e;                                                                 \
        asm("mov.b64 %0, {%1,%2};" : "=l"(_e) : "f"(_f.x), "f"(_f.y));          \
        asm("fma.rn.f32x2 %0, %1, %2, %0;" : "+l"(acc) : "l"(uval), "l"(_e));   \
    } while (0)

__device__ __forceinline__ float site_partial(
        uint4 a0, uint4 a1, uint4 a2, uint4 a3, const ulonglong2* ub) {
    // ub[4k] = { u[16q+2k], u[16q+2k+1] },  a_c component k -> in = 16q + 4c + k
    ulonglong2 u0 = ub[0],  u1 = ub[4],  u2 = ub[8],  u3 = ub[12];
    ulonglong2 u4 = ub[16], u5 = ub[20], u6 = ub[24], u7 = ub[28];
    u64 c0 = 0ull, c1 = 0ull, c2 = 0ull, c3 = 0ull;
    ACC(c0, a0.x, u0.x); ACC(c1, a0.y, u0.y); ACC(c2, a0.z, u1.x); ACC(c3, a0.w, u1.y);
    ACC(c0, a1.x, u2.x); ACC(c1, a1.y, u2.y); ACC(c2, a1.z, u3.x); ACC(c3, a1.w, u3.y);
    ACC(c0, a2.x, u4.x); ACC(c1, a2.y, u4.y); ACC(c2, a2.z, u5.x); ACC(c3, a2.w, u5.y);
    ACC(c0, a3.x, u6.x); ACC(c1, a3.y, u6.y); ACC(c2, a3.z, u7.x); ACC(c3, a3.w, u7.y);
    float l0, h0, l1, h1, l2, h2, l3, h3;
    asm("mov.b64 {%0,%1}, %2;" : "=f"(l0), "=f"(h0) : "l"(c0));
    asm("mov.b64 {%0,%1}, %2;" : "=f"(l1), "=f"(h1) : "l"(c1));
    asm("mov.b64 {%0,%1}, %2;" : "=f"(l2), "=f"(h2) : "l"(c2));
    asm("mov.b64 {%0,%1}, %2;" : "=f"(l3), "=f"(h3) : "l"(c3));
    return ((l0 + h0) + (l1 + h1)) + ((l2 + h2) + (l3 + h3));
}

// ---------- chain ----------
// grid 128: side = bx>>6, b = bx&63. 256 threads; warp w owns out = 8w..8w+7,
// lane = rloc*4 + q; q handles in = 16q..16q+15. One __syncthreads per site.
__global__ void __launch_bounds__(256, 1)
chain_kernel(const float* __restrict__ x) {
    __shared__ float2 xsh[L_];
    __shared__ __align__(16) ulonglong2 usm[2][32];  // [(in&15)>>1]*4 + (in>>4)

    int tid = threadIdx.x;
    int lane = tid & 31, w = tid >> 5;
    int q = lane & 3;
    int out = w * 8 + (lane >> 2);
    int side = blockIdx.x >> 6;
    int b = blockIdx.x & 63;
    bool owner = (q == 0);

    const float2* xsrc = (const float2*)x + (size_t)b * S_ + side * L_;
    for (int i = tid; i < L_; i += 256)
        xsh[i] = xsrc[side ? (L_ - 1 - i) : i];
    if (tid < 32) { usm[0][tid].x = 0ull; usm[0][tid].y = 0ull; }
    __syncthreads();
    if (tid == 0) {                                  // v = e0 -> u[0] = (x0, x1)
        float2 x0 = xsh[0];
        u64 z;
        asm("mov.b64 %0, {%1,%2};" : "=l"(z) : "f"(x0.x), "f"(x0.y));
        usm[0][0].x = z;
    }
    float v = (out == 0) ? 1.0f : 0.0f;
    // owner's u slot for in = out
    int wslot = (((out & 15) >> 1) << 2) + (out >> 4);
    int whalf = out & 1;
    const ulonglong2* ub0 = &usm[0][q];
    const ulonglong2* ub1 = &usm[1][q];

    const uint4* Ep = (const uint4*)g_E + ((size_t)side << 19) + tid * 4;
    uint4 A0, A1, A2, A3, B0, B1, B2, B3;
    {
        const uint4* p = Ep;
        A0 = __ldg(p); A1 = __ldg(p + 1); A2 = __ldg(p + 2); A3 = __ldg(p + 3);
        p += 1024;
        B0 = __ldg(p); B1 = __ldg(p + 1); B2 = __ldg(p + 2); B3 = __ldg(p + 3);
    }

    for (int s = 0; s < L_; s += 2) {
        // ---- even site s (buffer A, u parity 0) ----
        {
            float2 xc = xsh[s];
            float2 xn = xsh[s + 1];
            __syncthreads();
            float ps = site_partial(A0, A1, A2, A3, ub0);
            if (s + 2 < L_) {                        // reload A <- s+2 (~2 sites lead)
                const uint4* p = Ep + (size_t)(s + 2) * 1024;
                A0 = __ldg(p); A1 = __ldg(p + 1); A2 = __ldg(p + 2); A3 = __ldg(p + 3);
            }
            ps += __shfl_xor_sync(0xFFFFFFFFu, ps, 1);
            ps += __shfl_xor_sync(0xFFFFFFFFu, ps, 2);
            if (owner) {
                float vp = ps + v * (xc.x + xc.y);
                v = vp;
                u64 st;
                asm("mov.b64 %0, {%1,%2};" : "=l"(st) : "f"(vp * xn.x), "f"(vp * xn.y));
                ((u64*)&usm[1][wslot])[whalf] = st;
            }
        }
        // ---- odd site s+1 (buffer B, u parity 1) ----
        {
            float2 xc = xsh[s + 1];
            float2 xn = (s + 2 < L_) ? xsh[s + 2] : xc;
            __syncthreads();
            float ps = site_partial(B0, B1, B2, B3, ub1);
            if (s + 3 < L_) {                        // reload B <- s+3
                const uint4* p = Ep + (size_t)(s + 3) * 1024;
                B0 = __ldg(p); B1 = __ldg(p + 1); B2 = __ldg(p + 2); B3 = __ldg(p + 3);
            }
            ps += __shfl_xor_sync(0xFFFFFFFFu, ps, 1);
            ps += __shfl_xor_sync(0xFFFFFFFFu, ps, 2);
            if (owner) {
                float vp = ps + v * (xc.x + xc.y);
                v = vp;
                if (s + 2 < L_) {
                    u64 st;
                    asm("mov.b64 %0, {%1,%2};" : "=l"(st) : "f"(vp * xn.x), "f"(vp * xn.y));
                    ((u64*)&usm[0][wslot])[whalf] = st;
                }
            }
        }
    }
    if (owner) {
        if (side) g_wR[b][out] = v;
        else      g_vL[b][out] = v;
    }
}

// ---------- output: out[b][o] = sum_l vL[l] * sum_r core[o][l][r] * wR[r] ----------
__global__ void __launch_bounds__(640, 1)
output_kernel(const float* __restrict__ core, float* __restrict__ out) {
    int b = blockIdx.x;
    int tid = threadIdx.x;              // 640 = 10 o * 64 l
    int o = tid >> 6, l = tid & 63;
    __shared__ float wsh[D_];
    __shared__ float red[O_][2];
    if (tid < 64) wsh[tid] = g_wR[b][tid];
    __syncthreads();
    const float4* c4 = (const float4*)(core + (o * D_ + l) * D_);
    const float4* w4 = (const float4*)wsh;
    float s = 0.f;
    #pragma unroll
    for (int k = 0; k < 16; k++) {
        float4 cv = c4[k], wv = w4[k];
        s += cv.x * wv.x + cv.y * wv.y + cv.z * wv.z + cv.w * wv.w;
    }
    s *= g_vL[b][l];
    #pragma unroll
    for (int off = 16; off; off >>= 1) s += __shfl_xor_sync(0xFFFFFFFFu, s, off);
    if ((tid & 31) == 0) red[o][(tid >> 5) & 1] = s;
    __syncthreads();
    if (tid < O_) out[b * O_ + tid] = red[tid][0] + red[tid][1];
}

extern "C" void kernel_launch(void* const* d_in, const int* in_sizes, int n_in,
                              void* d_out, int out_size) {
    const float* x    = (const float*)d_in[0];   // [64, 1024, 2]
    const float* Wl   = (const float*)d_in[1];   // [512, 64, 64, 2]
    const float* core = (const float*)d_in[2];   // [10, 64, 64]
    const float* Wr   = (const float*)d_in[3];   // [512, 64, 64, 2]
    float* out = (float*)d_out;                  // [64, 10]

    prep_kernel<<<2 * L_, 256>>>(Wl, Wr);        // launch #1
    dummy_kernel<<<1, 32>>>(0);                  // launch #2
    dummy_kernel<<<1, 32>>>(1);                  // launch #3
    chain_kernel<<<128, 256>>>(x);               // launch #4 -> profiled
    output_kernel<<<B_, 640>>>(core, out);       // launch #5
}

// round 14
// speedup vs baseline: 1.4596x; 1.4596x over previous
#include <cuda_runtime.h>
#include <cuda_fp16.h>
#include <cstdint>

#define D_ 64
#define B_ 64
#define S_ 1024
#define L_ 512
#define O_ 10

typedef unsigned long long u64;

__device__ float g_vL[B_][D_];
__device__ float g_wR[B_][D_];
// fp16 E = W - I, scan-ordered, side-uniform, WARP-INTERLEAVED chunks:
// per site 1024 uint4; uint4 idx = w*128 + c*32 + lane
//   holds half2 E[in = (lane&3)*16 + c*4 + k][out = w*8 + (lane>>2)], k=0..3
__device__ __align__(16) uint32_t g_E[2 * L_ * 4096];

// ---------- prep ----------
__global__ void __launch_bounds__(256, 4) prep_kernel(
        const float* __restrict__ Wl, const float* __restrict__ Wr) {
    __shared__ float2 tile[D_ * (D_ + 1)];
    int bx = blockIdx.x;
    int side = bx >> 9;
    int s = bx & 511;
    int tid = threadIdx.x;
    if (side == 0) {
        const float2* src = (const float2*)Wl + (size_t)s * 4096;
        for (int i = tid; i < 4096; i += 256) {
            int l = i >> 6, r = i & 63;
            tile[l * 65 + r] = src[i];
        }
    } else {
        const float2* src = (const float2*)Wr + (size_t)(511 - s) * 4096;
        for (int i = tid; i < 4096; i += 256) {
            int l = i >> 6, r = i & 63;
            tile[r * 65 + l] = src[i];
        }
    }
    __syncthreads();
    int lane = tid & 31, w = tid >> 5;
    int out = w * 8 + (lane >> 2);
    int q = lane & 3;
    uint4* dst = (uint4*)(g_E + (size_t)bx * 4096);
    #pragma unroll
    for (int c = 0; c < 4; c++) {
        uint4 o;
        uint32_t* op = &o.x;
        #pragma unroll
        for (int k = 0; k < 4; k++) {
            int in = q * 16 + c * 4 + k;
            float d = (in == out) ? 1.0f : 0.0f;
            float2 wv = tile[in * 65 + out];
            __half2 h = __floats2half2_rn(wv.x - d, wv.y - d);
            op[k] = *(uint32_t*)&h;
        }
        dst[w * 128 + c * 32 + lane] = o;     // warp-contiguous 512B per chunk
    }
}

// profiling-only slot rotators (keep chain at launch #4)
__global__ void dummy_kernel(int v) { if (v == 12345) g_vL[0][0] = 0.f; }

// ---------- per-site partial: FULLY scalar, zero arrays ----------
#define ACC(acc, hword, uval) do {                                              \
        uint32_t _h = (hword);                                                  \
        float2 _f = __half22float2(*(__half2*)&_h);                             \
        u64 _e;                                                                 \
        asm("mov.b64 %0, {%1,%2};" : "=l"(_e) : "f"(_f.x), "f"(_f.y));          \
        asm("fma.rn.f32x2 %0, %1, %2, %0;" : "+l"(acc) : "l"(uval), "l"(_e));   \
    } while (0)

__device__ __forceinline__ float site_partial(
        uint4 a0, uint4 a1, uint4 a2, uint4 a3, const ulonglong2* ub) {
    // ub[4k] = { u[16q+2k], u[16q+2k+1] };  a_c component k -> in = 16q + 4c + k
    ulonglong2 u0 = ub[0],  u1 = ub[4],  u2 = ub[8],  u3 = ub[12];
    ulonglong2 u4 = ub[16], u5 = ub[20], u6 = ub[24], u7 = ub[28];
    u64 c0 = 0ull, c1 = 0ull, c2 = 0ull, c3 = 0ull;
    ACC(c0, a0.x, u0.x); ACC(c1, a0.y, u0.y); ACC(c2, a0.z, u1.x); ACC(c3, a0.w, u1.y);
    ACC(c0, a1.x, u2.x); ACC(c1, a1.y, u2.y); ACC(c2, a1.z, u3.x); ACC(c3, a1.w, u3.y);
    ACC(c0, a2.x, u4.x); ACC(c1, a2.y, u4.y); ACC(c2, a2.z, u5.x); ACC(c3, a2.w, u5.y);
    ACC(c0, a3.x, u6.x); ACC(c1, a3.y, u6.y); ACC(c2, a3.z, u7.x); ACC(c3, a3.w, u7.y);
    float l0, h0, l1, h1, l2, h2, l3, h3;
    asm("mov.b64 {%0,%1}, %2;" : "=f"(l0), "=f"(h0) : "l"(c0));
    asm("mov.b64 {%0,%1}, %2;" : "=f"(l1), "=f"(h1) : "l"(c1));
    asm("mov.b64 {%0,%1}, %2;" : "=f"(l2), "=f"(h2) : "l"(c2));
    asm("mov.b64 {%0,%1}, %2;" : "=f"(l3), "=f"(h3) : "l"(c3));
    return ((l0 + h0) + (l1 + h1)) + ((l2 + h2) + (l3 + h3));
}

// ---------- chain ----------
// grid 128: side = bx>>6, b = bx&63. 256 threads; warp w owns out = 8w..8w+7,
// lane = rloc*4 + q; q handles in = 16q..16q+15. One __syncthreads per site.
__global__ void __launch_bounds__(256, 1)
chain_kernel(const float* __restrict__ x) {
    __shared__ float2 xsh[L_];
    __shared__ __align__(16) ulonglong2 usm[2][32];  // [(in&15)>>1]*4 + (in>>4)

    int tid = threadIdx.x;
    int lane = tid & 31, w = tid >> 5;
    int q = lane & 3;
    int out = w * 8 + (lane >> 2);
    int side = blockIdx.x >> 6;
    int b = blockIdx.x & 63;
    bool owner = (q == 0);

    const float2* xsrc = (const float2*)x + (size_t)b * S_ + side * L_;
    for (int i = tid; i < L_; i += 256)
        xsh[i] = xsrc[side ? (L_ - 1 - i) : i];
    if (tid < 32) { usm[0][tid].x = 0ull; usm[0][tid].y = 0ull; }
    __syncthreads();
    if (tid == 0) {                                  // v = e0 -> u[0] = (x0, x1)
        float2 x0 = xsh[0];
        u64 z;
        asm("mov.b64 %0, {%1,%2};" : "=l"(z) : "f"(x0.x), "f"(x0.y));
        usm[0][0].x = z;
    }
    float v = (out == 0) ? 1.0f : 0.0f;
    int wslot = (((out & 15) >> 1) << 2) + (out >> 4);
    int whalf = out & 1;
    const ulonglong2* ub0 = &usm[0][q];
    const ulonglong2* ub1 = &usm[1][q];

    // warp-interleaved E: lane base, chunk stride 32 uint4 (512B)
    const uint4* Ep = (const uint4*)g_E + ((size_t)side << 19) + w * 128 + lane;
    uint4 A0, A1, A2, A3, B0, B1, B2, B3;
    {
        const uint4* p = Ep;
        A0 = __ldg(p); A1 = __ldg(p + 32); A2 = __ldg(p + 64); A3 = __ldg(p + 96);
        p += 1024;
        B0 = __ldg(p); B1 = __ldg(p + 32); B2 = __ldg(p + 64); B3 = __ldg(p + 96);
    }

    for (int s = 0; s < L_; s += 2) {
        // ---- even site s (buffer A, u parity 0) ----
        {
            float2 xc = xsh[s];
            float2 xn = xsh[s + 1];
            __syncthreads();
            float ps = site_partial(A0, A1, A2, A3, ub0);
            if (s + 2 < L_) {                        // reload A <- s+2 (~2 sites lead)
                const uint4* p = Ep + (size_t)(s + 2) * 1024;
                A0 = __ldg(p); A1 = __ldg(p + 32); A2 = __ldg(p + 64); A3 = __ldg(p + 96);
            }
            ps += __shfl_xor_sync(0xFFFFFFFFu, ps, 1);
            ps += __shfl_xor_sync(0xFFFFFFFFu, ps, 2);
            if (owner) {
                float vp = ps + v * (xc.x + xc.y);
                v = vp;
                u64 st;
                asm("mov.b64 %0, {%1,%2};" : "=l"(st) : "f"(vp * xn.x), "f"(vp * xn.y));
                ((u64*)&usm[1][wslot])[whalf] = st;
            }
        }
        // ---- odd site s+1 (buffer B, u parity 1) ----
        {
            float2 xc = xsh[s + 1];
            float2 xn = (s + 2 < L_) ? xsh[s + 2] : xc;
            __syncthreads();
            float ps = site_partial(B0, B1, B2, B3, ub1);
            if (s + 3 < L_) {                        // reload B <- s+3
                const uint4* p = Ep + (size_t)(s + 3) * 1024;
                B0 = __ldg(p); B1 = __ldg(p + 32); B2 = __ldg(p + 64); B3 = __ldg(p + 96);
            }
            ps += __shfl_xor_sync(0xFFFFFFFFu, ps, 1);
            ps += __shfl_xor_sync(0xFFFFFFFFu, ps, 2);
            if (owner) {
                float vp = ps + v * (xc.x + xc.y);
                v = vp;
                if (s + 2 < L_) {
                    u64 st;
                    asm("mov.b64 %0, {%1,%2};" : "=l"(st) : "f"(vp * xn.x), "f"(vp * xn.y));
                    ((u64*)&usm[0][wslot])[whalf] = st;
                }
            }
        }
    }
    if (owner) {
        if (side) g_wR[b][out] = v;
        else      g_vL[b][out] = v;
    }
}

// ---------- output: out[b][o] = sum_l vL[l] * sum_r core[o][l][r] * wR[r] ----------
__global__ void __launch_bounds__(640, 1)
output_kernel(const float* __restrict__ core, float* __restrict__ out) {
    int b = blockIdx.x;
    int tid = threadIdx.x;              // 640 = 10 o * 64 l
    int o = tid >> 6, l = tid & 63;
    __shared__ float wsh[D_];
    __shared__ float red[O_][2];
    if (tid < 64) wsh[tid] = g_wR[b][tid];
    __syncthreads();
    const float4* c4 = (const float4*)(core + (o * D_ + l) * D_);
    const float4* w4 = (const float4*)wsh;
    float s = 0.f;
    #pragma unroll
    for (int k = 0; k < 16; k++) {
        float4 cv = c4[k], wv = w4[k];
        s += cv.x * wv.x + cv.y * wv.y + cv.z * wv.z + cv.w * wv.w;
    }
    s *= g_vL[b][l];
    #pragma unroll
    for (int off = 16; off; off >>= 1) s += __shfl_xor_sync(0xFFFFFFFFu, s, off);
    if ((tid & 31) == 0) red[o][(tid >> 5) & 1] = s;
    __syncthreads();
    if (tid < O_) out[b * O_ + tid] = red[tid][0] + red[tid][1];
}

extern "C" void kernel_launch(void* const* d_in, const int* in_sizes, int n_in,
                              void* d_out, int out_size) {
    const float* x    = (const float*)d_in[0];   // [64, 1024, 2]
    const float* Wl   = (const float*)d_in[1];   // [512, 64, 64, 2]
    const float* core = (const float*)d_in[2];   // [10, 64, 64]
    const float* Wr   = (const float*)d_in[3];   // [512, 64, 64, 2]
    float* out = (float*)d_out;                  // [64, 10]

    prep_kernel<<<2 * L_, 256>>>(Wl, Wr);        // launch #1
    dummy_kernel<<<1, 32>>>(0);                  // launch #2
    dummy_kernel<<<1, 32>>>(1);                  // launch #3
    chain_kernel<<<128, 256>>>(x);               // launch #4 -> profiled
    output_kernel<<<B_, 640>>>(core, out);       // launch #5
}

// round 16
// speedup vs baseline: 1.5503x; 1.0621x over previous
#include <cuda_runtime.h>
#include <cuda_fp16.h>
#include <cstdint>

#define D_ 64
#define B_ 64
#define S_ 1024
#define L_ 512
#define O_ 10

typedef unsigned long long u64;

__device__ float g_vL[B_][D_];
__device__ float g_wR[B_][D_];
// fp16 E = W - I, scan-ordered, side-uniform, WARP-INTERLEAVED chunks:
// uint4 idx = w*128 + c*32 + lane holds half2 E[in=(lane&3)*16+c*4+k][out=w*8+(lane>>2)]
__device__ __align__(16) uint32_t g_E[2 * L_ * 4096];

// ---------- prep (unchanged, proven) ----------
__global__ void __launch_bounds__(256, 4) prep_kernel(
        const float* __restrict__ Wl, const float* __restrict__ Wr) {
    __shared__ float2 tile[D_ * (D_ + 1)];
    int bx = blockIdx.x;
    int side = bx >> 9;
    int s = bx & 511;
    int tid = threadIdx.x;
    if (side == 0) {
        const float2* src = (const float2*)Wl + (size_t)s * 4096;
        for (int i = tid; i < 4096; i += 256) {
            int l = i >> 6, r = i & 63;
            tile[l * 65 + r] = src[i];
        }
    } else {
        const float2* src = (const float2*)Wr + (size_t)(511 - s) * 4096;
        for (int i = tid; i < 4096; i += 256) {
            int l = i >> 6, r = i & 63;
            tile[r * 65 + l] = src[i];
        }
    }
    __syncthreads();
    int lane = tid & 31, w = tid >> 5;
    int out = w * 8 + (lane >> 2);
    int q = lane & 3;
    uint4* dst = (uint4*)(g_E + (size_t)bx * 4096);
    #pragma unroll
    for (int c = 0; c < 4; c++) {
        uint4 o;
        uint32_t* op = &o.x;
        #pragma unroll
        for (int k = 0; k < 4; k++) {
            int in = q * 16 + c * 4 + k;
            float d = (in == out) ? 1.0f : 0.0f;
            float2 wv = tile[in * 65 + out];
            __half2 h = __floats2half2_rn(wv.x - d, wv.y - d);
            op[k] = *(uint32_t*)&h;
        }
        dst[w * 128 + c * 32 + lane] = o;
    }
}

// profiling-only slot rotators (keep chain at launch #4)
__global__ void dummy_kernel(int v) { if (v == 12345) g_vL[0][0] = 0.f; }

// ---------- helper macros (fully scalar; no arrays) ----------
#define CVT1(EF, HW) do {                                                       \
        uint32_t _h = (HW);                                                     \
        float2 _f = __half22float2(*(__half2*)&_h);                             \
        asm("mov.b64 %0, {%1,%2};" : "=l"(EF) : "f"(_f.x), "f"(_f.y));          \
    } while (0)
// convert raw fp16 site (R0..R3) into packed fp32 Ef0..Ef15 (off critical path)
#define CVT16(R0, R1, R2, R3) do {                                              \
        CVT1(Ef0,  R0.x); CVT1(Ef1,  R0.y); CVT1(Ef2,  R0.z); CVT1(Ef3,  R0.w);\
        CVT1(Ef4,  R1.x); CVT1(Ef5,  R1.y); CVT1(Ef6,  R1.z); CVT1(Ef7,  R1.w);\
        CVT1(Ef8,  R2.x); CVT1(Ef9,  R2.y); CVT1(Ef10, R2.z); CVT1(Ef11, R2.w);\
        CVT1(Ef12, R3.x); CVT1(Ef13, R3.y); CVT1(Ef14, R3.z); CVT1(Ef15, R3.w);\
    } while (0)
#define FMA2(ACC, EF, UV) \
    asm("fma.rn.f32x2 %0, %1, %2, %0;" : "+l"(ACC) : "l"(UV), "l"(EF))
#define ADD2(DST, A, Bv) \
    asm("add.rn.f32x2 %0, %1, %2;" : "=l"(DST) : "l"(A), "l"(Bv))

// ---------- chain ----------
// grid 128: side = bx>>6, b = bx&63. 256 threads; warp w owns out = 8w..8w+7,
// lane = rloc*4 + q; q handles in = 16q..16q+15. One __syncthreads per site.
// Iteration: bar -> LDS u -> 16 FFMA2 (pre-packed Ef) -> [cvt next site W,
// LDG site+2 raw: shadow work] -> packed-add reduce -> 2 shfl -> owner update.
__global__ void __launch_bounds__(256, 1)
chain_kernel(const float* __restrict__ x) {
    __shared__ float2 xsh[L_];
    __shared__ __align__(16) ulonglong2 usm[2][32];  // [(in&15)>>1]*4 + (in>>4)

    int tid = threadIdx.x;
    int lane = tid & 31, w = tid >> 5;
    int q = lane & 3;
    int out = w * 8 + (lane >> 2);
    int side = blockIdx.x >> 6;
    int b = blockIdx.x & 63;
    bool owner = (q == 0);

    const float2* xsrc = (const float2*)x + (size_t)b * S_ + side * L_;
    for (int i = tid; i < L_; i += 256)
        xsh[i] = xsrc[side ? (L_ - 1 - i) : i];
    if (tid < 32) { usm[0][tid].x = 0ull; usm[0][tid].y = 0ull; }
    __syncthreads();
    if (tid == 0) {                                  // v = e0 -> u[0] = (x0, x1)
        float2 x0 = xsh[0];
        u64 z;
        asm("mov.b64 %0, {%1,%2};" : "=l"(z) : "f"(x0.x), "f"(x0.y));
        usm[0][0].x = z;
    }
    float v = (out == 0) ? 1.0f : 0.0f;
    int wslot = (((out & 15) >> 1) << 2) + (out >> 4);
    int whalf = out & 1;
    const ulonglong2* ub0 = &usm[0][q];
    const ulonglong2* ub1 = &usm[1][q];

    const uint4* Ep = (const uint4*)g_E + ((size_t)side << 19) + w * 128 + lane;
    u64 Ef0, Ef1, Ef2, Ef3, Ef4, Ef5, Ef6, Ef7;
    u64 Ef8, Ef9, Ef10, Ef11, Ef12, Ef13, Ef14, Ef15;
    uint4 A0, A1, A2, A3, B0, B1, B2, B3;
    {   // prologue: Ef <- site 0; rawB <- site 1; rawA <- site 2
        const uint4* p = Ep;
        A0 = __ldg(p); A1 = __ldg(p + 32); A2 = __ldg(p + 64); A3 = __ldg(p + 96);
        p += 1024;
        B0 = __ldg(p); B1 = __ldg(p + 32); B2 = __ldg(p + 64); B3 = __ldg(p + 96);
        CVT16(A0, A1, A2, A3);
        p += 1024;
        A0 = __ldg(p); A1 = __ldg(p + 32); A2 = __ldg(p + 64); A3 = __ldg(p + 96);
    }

#define SITE_BODY(UB, PARW, RN0, RN1, RN2, RN3, SNEXT2)  do {                   \
        float2 xc = xsh[s_];                                                    \
        float2 xn = (s_ < L_ - 1) ? xsh[s_ + 1] : xc;                           \
        __syncthreads();                                                        \
        ulonglong2 u0 = UB[0],  u1 = UB[4],  u2 = UB[8],  u3 = UB[12];          \
        ulonglong2 u4 = UB[16], u5 = UB[20], u6 = UB[24], u7 = UB[28];          \
        u64 c0 = 0ull, c1 = 0ull, c2 = 0ull, c3 = 0ull;                         \
        FMA2(c0, Ef0,  u0.x); FMA2(c1, Ef1,  u0.y);                             \
        FMA2(c2, Ef2,  u1.x); FMA2(c3, Ef3,  u1.y);                             \
        FMA2(c0, Ef4,  u2.x); FMA2(c1, Ef5,  u2.y);                             \
        FMA2(c2, Ef6,  u3.x); FMA2(c3, Ef7,  u3.y);                             \
        FMA2(c0, Ef8,  u4.x); FMA2(c1, Ef9,  u4.y);                             \
        FMA2(c2, Ef10, u5.x); FMA2(c3, Ef11, u5.y);                             \
        FMA2(c0, Ef12, u6.x); FMA2(c1, Ef13, u6.y);                             \
        FMA2(c2, Ef14, u7.x); FMA2(c3, Ef15, u7.y);                             \
        /* shadow work: convert next site, fetch site+2 into same raw buffer */ \
        CVT16(RN0, RN1, RN2, RN3);                                              \
        {                                                                       \
            int _i = (SNEXT2) < L_ - 1 ? (SNEXT2) : (L_ - 1);                   \
            const uint4* _p = Ep + (size_t)_i * 1024;                           \
            RN0 = __ldg(_p);      RN1 = __ldg(_p + 32);                         \
            RN2 = __ldg(_p + 64); RN3 = __ldg(_p + 96);                         \
        }                                                                       \
        u64 t0, t1;                                                             \
        ADD2(t0, c0, c1); ADD2(t1, c2, c3); ADD2(t0, t0, t1);                   \
        float lo, hi;                                                           \
        asm("mov.b64 {%0,%1}, %2;" : "=f"(lo), "=f"(hi) : "l"(t0));             \
        float ps = lo + hi;                                                     \
        ps += __shfl_xor_sync(0xFFFFFFFFu, ps, 1);                              \
        ps += __shfl_xor_sync(0xFFFFFFFFu, ps, 2);                              \
        if (owner) {                                                            \
            float vp = ps + v * (xc.x + xc.y);                                  \
            v = vp;                                                             \
            u64 st;                                                             \
            asm("mov.b64 %0, {%1,%2};" : "=l"(st)                               \
                : "f"(vp * xn.x), "f"(vp * xn.y));                              \
            ((u64*)&usm[PARW][wslot])[whalf] = st;                              \
        }                                                                       \
    } while (0)

    for (int s = 0; s < L_; s += 2) {
        {   // even site s: u parity 0; next site raw in B; fetch s+3 into B
            int s_ = s;
            SITE_BODY(ub0, 1, B0, B1, B2, B3, s + 3);
        }
        {   // odd site s+1: u parity 1; next site raw in A; fetch s+4 into A
            int s_ = s + 1;
            SITE_BODY(ub1, 0, A0, A1, A2, A3, s + 4);
        }
    }
#undef SITE_BODY

    if (owner) {
        if (side) g_wR[b][out] = v;
        else      g_vL[b][out] = v;
    }
}

// ---------- output: out[b][o] = sum_l vL[l] * sum_r core[o][l][r] * wR[r] ----------
__global__ void __launch_bounds__(640, 1)
output_kernel(const float* __restrict__ core, float* __restrict__ out) {
    int b = blockIdx.x;
    int tid = threadIdx.x;              // 640 = 10 o * 64 l
    int o = tid >> 6, l = tid & 63;
    __shared__ float wsh[D_];
    __shared__ float red[O_][2];
    if (tid < 64) wsh[tid] = g_wR[b][tid];
    __syncthreads();
    const float4* c4 = (const float4*)(core + (o * D_ + l) * D_);
    const float4* w4 = (const float4*)wsh;
    float s = 0.f;
    #pragma unroll
    for (int k = 0; k < 16; k++) {
        float4 cv = c4[k], wv = w4[k];
        s += cv.x * wv.x + cv.y * wv.y + cv.z * wv.z + cv.w * wv.w;
    }
    s *= g_vL[b][l];
    #pragma unroll
    for (int off = 16; off; off >>= 1) s += __shfl_xor_sync(0xFFFFFFFFu, s, off);
    if ((tid & 31) == 0) red[o][(tid >> 5) & 1] = s;
    __syncthreads();
    if (tid < O_) out[b * O_ + tid] = red[tid][0] + red[tid][1];
}

extern "C" void kernel_launch(void* const* d_in, const int* in_sizes, int n_in,
                              void* d_out, int out_size) {
    const float* x    = (const float*)d_in[0];   // [64, 1024, 2]
    const float* Wl   = (const float*)d_in[1];   // [512, 64, 64, 2]
    const float* core = (const float*)d_in[2];   // [10, 64, 64]
    const float* Wr   = (const float*)d_in[3];   // [512, 64, 64, 2]
    float* out = (float*)d_out;                  // [64, 10]

    prep_kernel<<<2 * L_, 256>>>(Wl, Wr);        // launch #1
    dummy_kernel<<<1, 32>>>(0);                  // launch #2
    dummy_kernel<<<1, 32>>>(1);                  // launch #3
    chain_kernel<<<128, 256>>>(x);               // launch #4 -> profiled
    output_kernel<<<B_, 640>>>(core, out);       // launch #5
}